// round 16
// baseline (speedup 1.0000x reference)
#include <cuda_runtime.h>
#include <cuda_fp16.h>
#include <cstdint>
#include <math.h>

// Problem constants
#define D_MODEL 1280
#define NHEAD   20
#define DHEAD   64
#define BATCH   4
#define SEQ     1024
#define BHEADS  (BATCH*NHEAD)      // 80
#define M_TOTAL (BATCH*SEQ)        // 4096
#define ALPHA_C 0.48f
#define SM_SCALE 0.125f

typedef uint32_t u32;

// ---------------- scratch (device globals; referenced ONLY from device code) --
__device__ __align__(16) __half g_xh[M_TOTAL * D_MODEL];   // hs fp16
__device__ __align__(16) __half g_qh[M_TOTAL * D_MODEL];   // Q * SM_SCALE, fp16
__device__ __align__(16) __half g_kh[M_TOTAL * D_MODEL];
__device__ __align__(16) __half g_vh[M_TOTAL * D_MODEL];
__device__ __align__(16) __half g_ah[M_TOTAL * D_MODEL];   // attention output fp16
__device__ __align__(16) __half g_wt[4 * D_MODEL * D_MODEL]; // W^T fp16, [w][n*K+k]
__device__ __align__(16) __half g_kbh[BHEADS * SEQ * DHEAD]; // alpha*K_bg fp16
__device__ __align__(16) __half g_vbh[BHEADS * SEQ * DHEAD]; // alpha*V_bg fp16

// ---------------- helpers ----------------
__device__ __forceinline__ u32 smem_u32(const void* p) {
    u32 a;
    asm("{ .reg .u64 t; cvta.to.shared.u64 t, %1; cvt.u32.u64 %0, t; }"
        : "=r"(a) : "l"(p));
    return a;
}
__device__ __forceinline__ u32 pkh2(float lo, float hi) {
    __half2 h = __floats2half2_rn(lo, hi);
    return *(u32*)&h;
}
__device__ __forceinline__ void ldm_x4(u32 addr, u32 r[4]) {
    asm volatile("ldmatrix.sync.aligned.m8n8.x4.shared.b16 {%0,%1,%2,%3}, [%4];"
                 : "=r"(r[0]), "=r"(r[1]), "=r"(r[2]), "=r"(r[3]) : "r"(addr));
}
__device__ __forceinline__ void ldm_x4_t(u32 addr, u32 r[4]) {
    asm volatile("ldmatrix.sync.aligned.m8n8.x4.trans.shared.b16 {%0,%1,%2,%3}, [%4];"
                 : "=r"(r[0]), "=r"(r[1]), "=r"(r[2]), "=r"(r[3]) : "r"(addr));
}
__device__ __forceinline__ void mma16816(float d[4], const u32 a[4], u32 b0, u32 b1) {
    asm volatile(
        "mma.sync.aligned.m16n8k16.row.col.f32.f16.f16.f32 "
        "{%0,%1,%2,%3},{%4,%5,%6,%7},{%8,%9},{%0,%1,%2,%3};"
        : "+f"(d[0]), "+f"(d[1]), "+f"(d[2]), "+f"(d[3])
        : "r"(a[0]), "r"(a[1]), "r"(a[2]), "r"(a[3]), "r"(b0), "r"(b1));
}
__device__ __forceinline__ void cpa16(u32 s, const void* g) {
    asm volatile("cp.async.cg.shared.global [%0], [%1], 16;" :: "r"(s), "l"(g));
}
#define CP_COMMIT() asm volatile("cp.async.commit_group;" ::: "memory")
#define CP_WAIT0()  asm volatile("cp.async.wait_group 0;" ::: "memory")
#define CP_WAIT1()  asm volatile("cp.async.wait_group 1;" ::: "memory")

// ---------------- prep kernels ----------------
__global__ __launch_bounds__(256) void conv_kernel(const float* __restrict__ src)
{
    const int i = (blockIdx.x * 256 + threadIdx.x) * 8;
    float4 a = *(const float4*)(src + i);
    float4 b = *(const float4*)(src + i + 4);
    uint4 o;
    o.x = pkh2(a.x, a.y); o.y = pkh2(a.z, a.w);
    o.z = pkh2(b.x, b.y); o.w = pkh2(b.z, b.w);
    *(uint4*)(g_xh + i) = o;
}

__global__ __launch_bounds__(256) void conv_bg_kernel(const float* __restrict__ Kbg,
                                                      const float* __restrict__ Vbg)
{
    const int i = (blockIdx.x * 256 + threadIdx.x) * 8;
    float4 a = *(const float4*)(Kbg + i);
    float4 b = *(const float4*)(Kbg + i + 4);
    uint4 o;
    o.x = pkh2(a.x * ALPHA_C, a.y * ALPHA_C); o.y = pkh2(a.z * ALPHA_C, a.w * ALPHA_C);
    o.z = pkh2(b.x * ALPHA_C, b.y * ALPHA_C); o.w = pkh2(b.z * ALPHA_C, b.w * ALPHA_C);
    *(uint4*)(g_kbh + i) = o;
    a = *(const float4*)(Vbg + i);
    b = *(const float4*)(Vbg + i + 4);
    o.x = pkh2(a.x * ALPHA_C, a.y * ALPHA_C); o.y = pkh2(a.z * ALPHA_C, a.w * ALPHA_C);
    o.z = pkh2(b.x * ALPHA_C, b.y * ALPHA_C); o.w = pkh2(b.z * ALPHA_C, b.w * ALPHA_C);
    *(uint4*)(g_vbh + i) = o;
}

__global__ __launch_bounds__(256) void prep_w_kernel(const float* __restrict__ Wq,
                                                     const float* __restrict__ Wk,
                                                     const float* __restrict__ Wv,
                                                     const float* __restrict__ Wo)
{
    const int w = blockIdx.z;
    const float* W = (w == 0) ? Wq : (w == 1) ? Wk : (w == 2) ? Wv : Wo;
    __half* dst = g_wt + (size_t)w * D_MODEL * D_MODEL;

    __shared__ float t[32][33];
    const int tx = threadIdx.x & 31, ty = threadIdx.x >> 5;   // 32x8
    const int n0 = blockIdx.x * 32, k0 = blockIdx.y * 32;
#pragma unroll
    for (int i = 0; i < 4; i++)
        t[ty + i * 8][tx] = W[(size_t)(k0 + ty + i * 8) * D_MODEL + n0 + tx];
    __syncthreads();
#pragma unroll
    for (int i = 0; i < 4; i++)
        dst[(size_t)(n0 + ty + i * 8) * D_MODEL + k0 + tx] =
            __float2half_rn(t[tx][ty + i * 8]);
}

// ---------------- fp16 mma.sync GEMM, BK=64 double-buffered cp.async ----------
#define MMST 72                 // halves per smem row (144B, conflict-free)
#define MMSTG (128 * MMST)      // halves per tile stage (9216)
#define MMSTGB (MMSTG * 2)      // bytes per tile stage (18432)
#define MM_DSMEM (4 * MMSTGB)   // A0,A1,B0,B1 = 73728 B
#define NKC2 (D_MODEL / 64)     // 20 k-stages

__device__ __forceinline__ void mm_body(const __half* __restrict__ A,
                                        const __half* __restrict__ Bt,
                                        __half* __restrict__ Ch,
                                        float* __restrict__ Cf,
                                        const float* __restrict__ bias,
                                        const float scale)
{
    extern __shared__ __align__(16) __half dsm[];

    const int tid  = threadIdx.x;
    const int wid  = tid >> 5;
    const int lane = tid & 31;
    const int g    = lane >> 2;
    const int t4   = lane & 3;

    const int brow = blockIdx.y * 128;
    const int bcol = blockIdx.x * 128;

    const int wm = wid >> 1, wn = wid & 1;
    const int m0 = wm * 32, n0 = wn * 64;

    const u32 base = smem_u32(dsm);
    // stage s: A at s*MMSTGB, B at 2*MMSTGB + s*MMSTGB

    // loader: row = tid>>1 (0..127), col base (tid&1)*32 halves, 4x16B per tensor
    const int lr = tid >> 1;
    const int lc = (tid & 1) * 32;
    const __half* Agp = A  + (size_t)(brow + lr) * D_MODEL + lc;
    const __half* Bgp = Bt + (size_t)(bcol + lr) * D_MODEL + lc;
    const u32 ldOff = (u32)((lr * MMST + lc) * 2);

    const u32 aPat = (u32)(((m0 + (lane & 15)) * MMST + 8 * (lane >> 4)) * 2);
    const u32 bPat = (u32)(((n0 + ((lane >> 4) << 3) + (lane & 7)) * MMST
                            + 8 * ((lane >> 3) & 1)) * 2);

    float acc[2][8][4];
#pragma unroll
    for (int i = 0; i < 2; i++)
#pragma unroll
        for (int j = 0; j < 8; j++)
#pragma unroll
            for (int q = 0; q < 4; q++) acc[i][j][q] = 0.f;

    auto issue_stage = [&](int kt) {
        const int koff = kt * 64;
        const u32 sa = base + (u32)((kt & 1) * MMSTGB) + ldOff;
        const u32 sb = base + (u32)(2 * MMSTGB + (kt & 1) * MMSTGB) + ldOff;
#pragma unroll
        for (int p = 0; p < 4; p++) {
            cpa16(sa + p * 16, Agp + koff + p * 8);
            cpa16(sb + p * 16, Bgp + koff + p * 8);
        }
        CP_COMMIT();
    };

    issue_stage(0);

    for (int kt = 0; kt < NKC2; kt++) {
        CP_WAIT0();
        __syncthreads();
        if (kt + 1 < NKC2) issue_stage(kt + 1);

        const u32 aA = base + (u32)((kt & 1) * MMSTGB) + aPat;
        const u32 bA = base + (u32)(2 * MMSTGB + (kt & 1) * MMSTGB) + bPat;
#pragma unroll
        for (int kk = 0; kk < 64; kk += 16) {
            u32 aF[2][4];
            ldm_x4(aA + kk * 2, aF[0]);
            ldm_x4(aA + (16 * MMST + kk) * 2, aF[1]);
            u32 bF[4][4];
#pragma unroll
            for (int p = 0; p < 4; p++)
                ldm_x4(bA + (p * 16 * MMST + kk) * 2, bF[p]);
#pragma unroll
            for (int mt = 0; mt < 2; mt++)
#pragma unroll
                for (int p = 0; p < 4; p++) {
                    mma16816(acc[mt][p * 2 + 0], aF[mt], bF[p][0], bF[p][1]);
                    mma16816(acc[mt][p * 2 + 1], aF[mt], bF[p][2], bF[p][3]);
                }
        }
    }

#pragma unroll
    for (int mt = 0; mt < 2; mt++) {
        const int r0 = brow + m0 + mt * 16 + g;
#pragma unroll
        for (int nj = 0; nj < 8; nj++) {
            const int col = bcol + n0 + nj * 8 + 2 * t4;
            float* d = acc[mt][nj];
            if (Ch) {
                *(u32*)&Ch[(size_t)r0 * D_MODEL + col] = pkh2(d[0] * scale, d[1] * scale);
                *(u32*)&Ch[(size_t)(r0 + 8) * D_MODEL + col] = pkh2(d[2] * scale, d[3] * scale);
            } else {
                float2 v;
                v.x = d[0] + bias[col]; v.y = d[1] + bias[col + 1];
                *(float2*)&Cf[(size_t)r0 * D_MODEL + col] = v;
                v.x = d[2] + bias[col]; v.y = d[3] + bias[col + 1];
                *(float2*)&Cf[(size_t)(r0 + 8) * D_MODEL + col] = v;
            }
        }
    }
}

__global__ __launch_bounds__(256) void qkv_mm_kernel()
{
    const int z = blockIdx.z;
    __half* C = (z == 0) ? g_qh : (z == 1) ? g_kh : g_vh;
    mm_body(g_xh, g_wt + (size_t)z * D_MODEL * D_MODEL, C, nullptr, nullptr,
            (z == 0) ? SM_SCALE : 1.0f);
}

__global__ __launch_bounds__(256) void out_mm_kernel(const float* __restrict__ bo,
                                                     float* __restrict__ out)
{
    mm_body(g_ah, g_wt + (size_t)3 * D_MODEL * D_MODEL, nullptr, out, bo, 1.0f);
}

// ---------------- register-resident flash attention, 3-stage cp.async ---------
#define QS 72
#define KVS 72
#define KVT 64
#define QB  (128 * QS * 2)        // Q bytes (18432)
#define KVHB (KVT * KVS * 2)      // one tensor tile bytes (9216)
#define STGB (2 * KVHB)           // K+V stage bytes (18432)
#define AT_DSMEM (QB + 3 * STGB)  // 73728 B
#define NIT ((2 * SEQ) / KVT)     // 32

__global__ __launch_bounds__(256) void attn_kernel()
{
    extern __shared__ __align__(16) __half dsm[];

    const int tid  = threadIdx.x;
    const int wid  = tid >> 5;
    const int lane = tid & 31;
    const int g    = lane >> 2;
    const int t4   = lane & 3;

    const int bh = blockIdx.y;
    const int b  = bh / NHEAD;
    const int h  = bh - b * NHEAD;
    const int q0 = blockIdx.x * 128;
    const int m0 = wid * 16;

    const u32 base = smem_u32(dsm);
    // layout: Q at 0; stage s: K at QB + s*STGB, V at QB + s*STGB + KVHB

    // tile loader: 256 threads x 2 rows x 16B per tensor
    const int klr = tid >> 3;            // 0..31
    const int klc = (tid & 7) * 8;       // halves
    const u32 ldOff = (u32)((klr * KVS + klc) * 2);

    auto issue_tile = [&](int it) {
        const int j0 = it * KVT;
        const u32 kD = base + QB + (u32)((it % 3) * STGB) + ldOff;
        const u32 vD = kD + KVHB;
#pragma unroll
        for (int p = 0; p < 2; p++) {
            const int row = klr + 32 * p;
            const __half *ks, *vs;
            if (j0 < SEQ) {
                const size_t off = (size_t)(b * SEQ + j0 + row) * D_MODEL + h * DHEAD + klc;
                ks = g_kh + off; vs = g_vh + off;
            } else {
                const size_t off = ((size_t)bh * SEQ + (j0 - SEQ + row)) * DHEAD + klc;
                ks = g_kbh + off; vs = g_vbh + off;
            }
            cpa16(kD + (u32)(32 * p * KVS * 2), ks);
            cpa16(vD + (u32)(32 * p * KVS * 2), vs);
        }
        CP_COMMIT();
    };

    // ---- load Q tile + prefetch kv tiles 0,1 ----
    {
        const __half* qg = g_qh + (size_t)(b * SEQ + q0) * D_MODEL + h * DHEAD;
#pragma unroll
        for (int p = 0; p < 2; p++) {
            const int idx = tid + 256 * p;
            const int r = idx >> 2;
            const int c = (idx & 3) * 16;
            *(uint4*)&dsm[r * QS + c]     = *(const uint4*)(qg + (size_t)r * D_MODEL + c);
            *(uint4*)&dsm[r * QS + c + 8] = *(const uint4*)(qg + (size_t)r * D_MODEL + c + 8);
        }
    }
    issue_tile(0);
    issue_tile(1);
    __syncthreads();

    // ---- preload Q fragments ----
    u32 qa[4][4];
    {
        const u32 qb = base + (u32)(((m0 + (lane & 15)) * QS + 8 * (lane >> 4)) * 2);
#pragma unroll
        for (int kk = 0; kk < 4; kk++) ldm_x4(qb + kk * 32, qa[kk]);
    }

    const u32 kPat = (u32)(((((lane >> 4) << 3) + (lane & 7)) * KVS
                            + 8 * ((lane >> 3) & 1)) * 2);
    const u32 vPat = (u32)(((8 * ((lane >> 3) & 1) + (lane & 7)) * KVS
                            + 8 * (lane >> 4)) * 2);

    float oacc[8][4];
#pragma unroll
    for (int i = 0; i < 8; i++)
#pragma unroll
        for (int j = 0; j < 4; j++) oacc[i][j] = 0.f;
    float m0r = -1e30f, m1r = -1e30f, l0r = 0.f, l1r = 0.f;

    for (int it = 0; it < NIT; it++) {
        CP_WAIT1();
        __syncthreads();
        if (it + 2 < NIT) issue_tile(it + 2);
        else CP_COMMIT();   // keep group-count invariant for wait_group 1

        const u32 kA = base + QB + (u32)((it % 3) * STGB) + kPat;
        const u32 vA = base + QB + (u32)((it % 3) * STGB) + (u32)KVHB + vPat;

        // ---- S = Q K^T : 16 x 64 in registers ----
        float sacc[8][4];
#pragma unroll
        for (int i = 0; i < 8; i++)
#pragma unroll
            for (int j = 0; j < 4; j++) sacc[i][j] = 0.f;
#pragma unroll
        for (int kk = 0; kk < 4; kk++) {
#pragma unroll
            for (int nb = 0; nb < 4; nb++) {
                u32 kb[4];
                ldm_x4(kA + (u32)((nb * 16 * KVS + kk * 16) * 2), kb);
                mma16816(sacc[nb * 2 + 0], qa[kk], kb[0], kb[1]);
                mma16816(sacc[nb * 2 + 1], qa[kk], kb[2], kb[3]);
            }
        }

        // ---- online softmax in registers ----
        float mx0 = m0r, mx1 = m1r;
#pragma unroll
        for (int nb = 0; nb < 8; nb++) {
            mx0 = fmaxf(mx0, fmaxf(sacc[nb][0], sacc[nb][1]));
            mx1 = fmaxf(mx1, fmaxf(sacc[nb][2], sacc[nb][3]));
        }
        mx0 = fmaxf(mx0, __shfl_xor_sync(0xFFFFFFFFu, mx0, 1));
        mx0 = fmaxf(mx0, __shfl_xor_sync(0xFFFFFFFFu, mx0, 2));
        mx1 = fmaxf(mx1, __shfl_xor_sync(0xFFFFFFFFu, mx1, 1));
        mx1 = fmaxf(mx1, __shfl_xor_sync(0xFFFFFFFFu, mx1, 2));

        const float sc0 = __expf(m0r - mx0);
        const float sc1 = __expf(m1r - mx1);
        m0r = mx0; m1r = mx1;

        float sum0 = 0.f, sum1 = 0.f;
#pragma unroll
        for (int nb = 0; nb < 8; nb++) {
            sacc[nb][0] = __expf(sacc[nb][0] - mx0); sum0 += sacc[nb][0];
            sacc[nb][1] = __expf(sacc[nb][1] - mx0); sum0 += sacc[nb][1];
            sacc[nb][2] = __expf(sacc[nb][2] - mx1); sum1 += sacc[nb][2];
            sacc[nb][3] = __expf(sacc[nb][3] - mx1); sum1 += sacc[nb][3];
        }
        sum0 += __shfl_xor_sync(0xFFFFFFFFu, sum0, 1);
        sum0 += __shfl_xor_sync(0xFFFFFFFFu, sum0, 2);
        sum1 += __shfl_xor_sync(0xFFFFFFFFu, sum1, 1);
        sum1 += __shfl_xor_sync(0xFFFFFFFFu, sum1, 2);
        l0r = l0r * sc0 + sum0;
        l1r = l1r * sc1 + sum1;

#pragma unroll
        for (int nb = 0; nb < 8; nb++) {
            oacc[nb][0] *= sc0; oacc[nb][1] *= sc0;
            oacc[nb][2] *= sc1; oacc[nb][3] *= sc1;
        }

        // ---- O += P V ----
#pragma unroll
        for (int kc = 0; kc < 4; kc++) {
            u32 pa[4];
            pa[0] = pkh2(sacc[kc * 2 + 0][0], sacc[kc * 2 + 0][1]);
            pa[1] = pkh2(sacc[kc * 2 + 0][2], sacc[kc * 2 + 0][3]);
            pa[2] = pkh2(sacc[kc * 2 + 1][0], sacc[kc * 2 + 1][1]);
            pa[3] = pkh2(sacc[kc * 2 + 1][2], sacc[kc * 2 + 1][3]);
#pragma unroll
            for (int dc = 0; dc < 4; dc++) {
                u32 vb[4];
                ldm_x4_t(vA + (u32)((kc * 16 * KVS + dc * 16) * 2), vb);
                mma16816(oacc[dc * 2 + 0], pa, vb[0], vb[1]);
                mma16816(oacc[dc * 2 + 1], pa, vb[2], vb[3]);
            }
        }
    }

    // ---- normalize + store fp16 ----
    {
        const float li0 = 1.0f / l0r;
        const float li1 = 1.0f / l1r;
        __half* baseo = g_ah + (size_t)(b * SEQ + q0 + m0 + g) * D_MODEL + h * DHEAD;
#pragma unroll
        for (int nb = 0; nb < 8; nb++) {
            const int col = nb * 8 + 2 * t4;
            *(u32*)(baseo + col) = pkh2(oacc[nb][0] * li0, oacc[nb][1] * li0);
            *(u32*)(baseo + 8 * D_MODEL + col) = pkh2(oacc[nb][2] * li1, oacc[nb][3] * li1);
        }
    }
}

// ---------------------------------------------------------------------------
extern "C" void kernel_launch(void* const* d_in, const int* in_sizes, int n_in,
                              void* d_out, int out_size)
{
    const float* hs  = (const float*)d_in[0];
    const float* Wq  = (const float*)d_in[1];
    const float* Wk  = (const float*)d_in[2];
    const float* Wv  = (const float*)d_in[3];
    const float* Wo  = (const float*)d_in[4];
    const float* bo  = (const float*)d_in[5];
    const float* Kbg = (const float*)d_in[6];
    const float* Vbg = (const float*)d_in[7];
    float* out = (float*)d_out;

    cudaFuncSetAttribute(qkv_mm_kernel, cudaFuncAttributeMaxDynamicSharedMemorySize, MM_DSMEM);
    cudaFuncSetAttribute(out_mm_kernel, cudaFuncAttributeMaxDynamicSharedMemorySize, MM_DSMEM);
    cudaFuncSetAttribute(attn_kernel,   cudaFuncAttributeMaxDynamicSharedMemorySize, AT_DSMEM);

    // 0) prep
    dim3 gw(D_MODEL / 32, D_MODEL / 32, 4);
    prep_w_kernel<<<gw, 256>>>(Wq, Wk, Wv, Wo);
    conv_kernel<<<(M_TOTAL * D_MODEL) / (256 * 8), 256>>>(hs);
    conv_bg_kernel<<<(BHEADS * SEQ * DHEAD) / (256 * 8), 256>>>(Kbg, Vbg);

    // 1) Q/K/V projections
    dim3 gqkv(D_MODEL / 128, M_TOTAL / 128, 3);
    qkv_mm_kernel<<<gqkv, 256, MM_DSMEM>>>();

    // 2) attention
    dim3 gattn(SEQ / 128, BHEADS);
    attn_kernel<<<gattn, 256, AT_DSMEM>>>();

    // 3) output projection + bias
    dim3 gout(D_MODEL / 128, M_TOTAL / 128, 1);
    out_mm_kernel<<<gout, 256, MM_DSMEM>>>(bo, out);
}

// round 17
// speedup vs baseline: 1.1997x; 1.1997x over previous
#include <cuda_runtime.h>
#include <cuda_fp16.h>
#include <cstdint>
#include <math.h>

// Problem constants
#define D_MODEL 1280
#define NHEAD   20
#define DHEAD   64
#define BATCH   4
#define SEQ     1024
#define BHEADS  (BATCH*NHEAD)      // 80
#define M_TOTAL (BATCH*SEQ)        // 4096
#define ALPHA_C 0.48f
#define SM_SCALE 0.125f

typedef uint32_t u32;

// ---------------- scratch (device globals; referenced ONLY from device code) --
__device__ __align__(16) __half g_xh[M_TOTAL * D_MODEL];   // hs fp16
__device__ __align__(16) __half g_qh[M_TOTAL * D_MODEL];   // Q * SM_SCALE, fp16
__device__ __align__(16) __half g_kh[M_TOTAL * D_MODEL];
__device__ __align__(16) __half g_vh[M_TOTAL * D_MODEL];
__device__ __align__(16) __half g_ah[M_TOTAL * D_MODEL];   // attention output fp16
__device__ __align__(16) __half g_wt[4 * D_MODEL * D_MODEL]; // W^T fp16, [w][n*K+k]
__device__ __align__(16) __half g_kbh[BHEADS * SEQ * DHEAD]; // alpha*K_bg fp16
__device__ __align__(16) __half g_vbh[BHEADS * SEQ * DHEAD]; // alpha*V_bg fp16

// ---------------- helpers ----------------
__device__ __forceinline__ u32 smem_u32(const void* p) {
    u32 a;
    asm("{ .reg .u64 t; cvta.to.shared.u64 t, %1; cvt.u32.u64 %0, t; }"
        : "=r"(a) : "l"(p));
    return a;
}
__device__ __forceinline__ u32 pkh2(float lo, float hi) {
    __half2 h = __floats2half2_rn(lo, hi);
    return *(u32*)&h;
}
__device__ __forceinline__ void ldm_x4(u32 addr, u32 r[4]) {
    asm volatile("ldmatrix.sync.aligned.m8n8.x4.shared.b16 {%0,%1,%2,%3}, [%4];"
                 : "=r"(r[0]), "=r"(r[1]), "=r"(r[2]), "=r"(r[3]) : "r"(addr));
}
__device__ __forceinline__ void ldm_x4_t(u32 addr, u32 r[4]) {
    asm volatile("ldmatrix.sync.aligned.m8n8.x4.trans.shared.b16 {%0,%1,%2,%3}, [%4];"
                 : "=r"(r[0]), "=r"(r[1]), "=r"(r[2]), "=r"(r[3]) : "r"(addr));
}
__device__ __forceinline__ void mma16816(float d[4], const u32 a[4], u32 b0, u32 b1) {
    asm volatile(
        "mma.sync.aligned.m16n8k16.row.col.f32.f16.f16.f32 "
        "{%0,%1,%2,%3},{%4,%5,%6,%7},{%8,%9},{%0,%1,%2,%3};"
        : "+f"(d[0]), "+f"(d[1]), "+f"(d[2]), "+f"(d[3])
        : "r"(a[0]), "r"(a[1]), "r"(a[2]), "r"(a[3]), "r"(b0), "r"(b1));
}
__device__ __forceinline__ void cpa16(u32 s, const void* g) {
    asm volatile("cp.async.cg.shared.global [%0], [%1], 16;" :: "r"(s), "l"(g));
}
#define CP_COMMIT() asm volatile("cp.async.commit_group;" ::: "memory")
#define CP_WAIT0()  asm volatile("cp.async.wait_group 0;" ::: "memory")

// ---------------- prep kernels ----------------
__global__ __launch_bounds__(256) void conv_kernel(const float* __restrict__ src)
{
    const int i = (blockIdx.x * 256 + threadIdx.x) * 8;
    float4 a = *(const float4*)(src + i);
    float4 b = *(const float4*)(src + i + 4);
    uint4 o;
    o.x = pkh2(a.x, a.y); o.y = pkh2(a.z, a.w);
    o.z = pkh2(b.x, b.y); o.w = pkh2(b.z, b.w);
    *(uint4*)(g_xh + i) = o;
}

__global__ __launch_bounds__(256) void conv_bg_kernel(const float* __restrict__ Kbg,
                                                      const float* __restrict__ Vbg)
{
    const int i = (blockIdx.x * 256 + threadIdx.x) * 8;
    float4 a = *(const float4*)(Kbg + i);
    float4 b = *(const float4*)(Kbg + i + 4);
    uint4 o;
    o.x = pkh2(a.x * ALPHA_C, a.y * ALPHA_C); o.y = pkh2(a.z * ALPHA_C, a.w * ALPHA_C);
    o.z = pkh2(b.x * ALPHA_C, b.y * ALPHA_C); o.w = pkh2(b.z * ALPHA_C, b.w * ALPHA_C);
    *(uint4*)(g_kbh + i) = o;
    a = *(const float4*)(Vbg + i);
    b = *(const float4*)(Vbg + i + 4);
    o.x = pkh2(a.x * ALPHA_C, a.y * ALPHA_C); o.y = pkh2(a.z * ALPHA_C, a.w * ALPHA_C);
    o.z = pkh2(b.x * ALPHA_C, b.y * ALPHA_C); o.w = pkh2(b.z * ALPHA_C, b.w * ALPHA_C);
    *(uint4*)(g_vbh + i) = o;
}

__global__ __launch_bounds__(256) void prep_w_kernel(const float* __restrict__ Wq,
                                                     const float* __restrict__ Wk,
                                                     const float* __restrict__ Wv,
                                                     const float* __restrict__ Wo)
{
    const int w = blockIdx.z;
    const float* W = (w == 0) ? Wq : (w == 1) ? Wk : (w == 2) ? Wv : Wo;
    __half* dst = g_wt + (size_t)w * D_MODEL * D_MODEL;

    __shared__ float t[32][33];
    const int tx = threadIdx.x & 31, ty = threadIdx.x >> 5;   // 32x8
    const int n0 = blockIdx.x * 32, k0 = blockIdx.y * 32;
#pragma unroll
    for (int i = 0; i < 4; i++)
        t[ty + i * 8][tx] = W[(size_t)(k0 + ty + i * 8) * D_MODEL + n0 + tx];
    __syncthreads();
#pragma unroll
    for (int i = 0; i < 4; i++)
        dst[(size_t)(n0 + ty + i * 8) * D_MODEL + k0 + tx] =
            __float2half_rn(t[tx][ty + i * 8]);
}

// ---------------- fp16 mma.sync GEMM: 128x64 block, 32x32 warps, 3 CTA/SM -----
#define AST 40
#define BST 40
#define ASTG (128 * AST)        // halves per A stage (5120)
#define BSTG (64 * BST)         // halves per B stage (2560)
#define NKC  (D_MODEL / 32)     // 40 k-chunks

__device__ __forceinline__ void mm_body(const __half* __restrict__ A,
                                        const __half* __restrict__ Bt,
                                        __half* __restrict__ Ch,
                                        float* __restrict__ Cf,
                                        const float* __restrict__ bias,
                                        const float scale)
{
    __shared__ __align__(16) __half As[2 * ASTG];
    __shared__ __align__(16) __half Bs[2 * BSTG];

    const int tid  = threadIdx.x;
    const int wid  = tid >> 5;
    const int lane = tid & 31;
    const int g    = lane >> 2;
    const int t4   = lane & 3;

    const int brow = blockIdx.y * 128;
    const int bcol = blockIdx.x * 64;

    const int wm = wid >> 1, wn = wid & 1;
    const int m0 = wm * 32, n0 = wn * 32;

    const u32 asb = smem_u32(As);
    const u32 bsb = smem_u32(Bs);

    // loaders: A chunks (tid: row=tid>>2, col=(tid&3)*8; + row+64), B chunk (row=tid>>2 of 64)
    const int ar = tid >> 2;
    const int ac = (tid & 3) * 8;
    const __half* Agp0 = A + (size_t)(brow + ar) * D_MODEL + ac;
    const __half* Agp1 = A + (size_t)(brow + ar + 64) * D_MODEL + ac;
    const __half* Bgp  = Bt + (size_t)(bcol + (tid >> 2)) * D_MODEL + ac;
    const u32 aDst0 = asb + (u32)((ar * AST + ac) * 2);
    const u32 aDst1 = aDst0 + (u32)(64 * AST * 2);
    const u32 bDst  = bsb + (u32)(((tid >> 2) * BST + ac) * 2);

    const u32 aPat = (u32)(((m0 + (lane & 15)) * AST + 8 * (lane >> 4)) * 2);
    const u32 bPat = (u32)(((n0 + ((lane >> 4) << 3) + (lane & 7)) * BST
                            + 8 * ((lane >> 3) & 1)) * 2);

    float acc[2][4][4];
#pragma unroll
    for (int i = 0; i < 2; i++)
#pragma unroll
        for (int j = 0; j < 4; j++)
#pragma unroll
            for (int q = 0; q < 4; q++) acc[i][j][q] = 0.f;

    auto issue_stage = [&](int kt) {
        const int koff = kt * 32;
        const u32 so = (u32)((kt & 1) ? ASTG * 2 : 0);
        const u32 sob = (u32)((kt & 1) ? BSTG * 2 : 0);
        cpa16(aDst0 + so, Agp0 + koff);
        cpa16(aDst1 + so, Agp1 + koff);
        cpa16(bDst + sob, Bgp + koff);
        CP_COMMIT();
    };

    issue_stage(0);

    for (int kt = 0; kt < NKC; kt++) {
        CP_WAIT0();
        __syncthreads();
        if (kt + 1 < NKC) issue_stage(kt + 1);

        const u32 aA = asb + (u32)((kt & 1) ? ASTG * 2 : 0) + aPat;
        const u32 bA = bsb + (u32)((kt & 1) ? BSTG * 2 : 0) + bPat;
#pragma unroll
        for (int kk = 0; kk < 32; kk += 16) {
            u32 aF[2][4];
            ldm_x4(aA + kk * 2, aF[0]);
            ldm_x4(aA + (16 * AST + kk) * 2, aF[1]);
            u32 bF[2][4];
#pragma unroll
            for (int p = 0; p < 2; p++)
                ldm_x4(bA + (p * 16 * BST + kk) * 2, bF[p]);
#pragma unroll
            for (int mt = 0; mt < 2; mt++)
#pragma unroll
                for (int p = 0; p < 2; p++) {
                    mma16816(acc[mt][p * 2 + 0], aF[mt], bF[p][0], bF[p][1]);
                    mma16816(acc[mt][p * 2 + 1], aF[mt], bF[p][2], bF[p][3]);
                }
        }
    }

#pragma unroll
    for (int mt = 0; mt < 2; mt++) {
        const int r0 = brow + m0 + mt * 16 + g;
#pragma unroll
        for (int nj = 0; nj < 4; nj++) {
            const int col = bcol + n0 + nj * 8 + 2 * t4;
            float* d = acc[mt][nj];
            if (Ch) {
                *(u32*)&Ch[(size_t)r0 * D_MODEL + col] = pkh2(d[0] * scale, d[1] * scale);
                *(u32*)&Ch[(size_t)(r0 + 8) * D_MODEL + col] = pkh2(d[2] * scale, d[3] * scale);
            } else {
                float2 v;
                v.x = d[0] + bias[col]; v.y = d[1] + bias[col + 1];
                *(float2*)&Cf[(size_t)r0 * D_MODEL + col] = v;
                v.x = d[2] + bias[col]; v.y = d[3] + bias[col + 1];
                *(float2*)&Cf[(size_t)(r0 + 8) * D_MODEL + col] = v;
            }
        }
    }
}

__global__ __launch_bounds__(256, 3) void qkv_mm_kernel()
{
    const int z = blockIdx.z;
    __half* C = (z == 0) ? g_qh : (z == 1) ? g_kh : g_vh;
    mm_body(g_xh, g_wt + (size_t)z * D_MODEL * D_MODEL, C, nullptr, nullptr,
            (z == 0) ? SM_SCALE : 1.0f);
}

__global__ __launch_bounds__(256, 3) void out_mm_kernel(const float* __restrict__ bo,
                                                        float* __restrict__ out)
{
    mm_body(g_ah, g_wt + (size_t)3 * D_MODEL * D_MODEL, nullptr, out, bo, 1.0f);
}

// ---------------- register-resident flash attention, cp.async pipelined -------
// (exactly the proven R15 kernel)
#define QS 72
#define KVS 72
#define KVT 64
#define KVB (KVT * KVS)        // halves per stage
#define NIT ((2 * SEQ) / KVT)  // 32

__global__ __launch_bounds__(256) void attn_kernel()
{
    __shared__ __align__(16) __half Qs[128 * QS];
    __shared__ __align__(16) __half Ks[2 * KVB];
    __shared__ __align__(16) __half Vs[2 * KVB];

    const int tid  = threadIdx.x;
    const int wid  = tid >> 5;
    const int lane = tid & 31;
    const int g    = lane >> 2;
    const int t4   = lane & 3;

    const int bh = blockIdx.y;
    const int b  = bh / NHEAD;
    const int h  = bh - b * NHEAD;
    const int q0 = blockIdx.x * 128;
    const int m0 = wid * 16;

    const u32 ksb = smem_u32(Ks);
    const u32 vsb = smem_u32(Vs);

    const int klr = tid >> 3;            // 0..31
    const int klc = (tid & 7) * 8;       // halves
    const u32 kDst = ksb + (u32)((klr * KVS + klc) * 2);
    const u32 vDst = vsb + (u32)((klr * KVS + klc) * 2);

    auto issue_tile = [&](int it) {
        const int j0 = it * KVT;
        const u32 so = (u32)((it & 1) ? KVB * 2 : 0);
#pragma unroll
        for (int p = 0; p < 2; p++) {
            const int row = klr + 32 * p;
            const __half *ks, *vs;
            if (j0 < SEQ) {
                const size_t off = (size_t)(b * SEQ + j0 + row) * D_MODEL + h * DHEAD + klc;
                ks = g_kh + off; vs = g_vh + off;
            } else {
                const size_t off = ((size_t)bh * SEQ + (j0 - SEQ + row)) * DHEAD + klc;
                ks = g_kbh + off; vs = g_vbh + off;
            }
            cpa16(kDst + so + (u32)(32 * p * KVS * 2), ks);
            cpa16(vDst + so + (u32)(32 * p * KVS * 2), vs);
        }
        CP_COMMIT();
    };

    // ---- load Q tile + prefetch kv tile 0 ----
    {
        const __half* qg = g_qh + (size_t)(b * SEQ + q0) * D_MODEL + h * DHEAD;
#pragma unroll
        for (int p = 0; p < 2; p++) {
            const int idx = tid + 256 * p;
            const int r = idx >> 2;
            const int c = (idx & 3) * 16;
            *(uint4*)&Qs[r * QS + c]     = *(const uint4*)(qg + (size_t)r * D_MODEL + c);
            *(uint4*)&Qs[r * QS + c + 8] = *(const uint4*)(qg + (size_t)r * D_MODEL + c + 8);
        }
    }
    issue_tile(0);
    __syncthreads();

    // ---- preload Q fragments ----
    u32 qa[4][4];
    {
        const u32 qsb = smem_u32(Qs);
        const u32 base = qsb + (u32)(((m0 + (lane & 15)) * QS + 8 * (lane >> 4)) * 2);
#pragma unroll
        for (int kk = 0; kk < 4; kk++) ldm_x4(base + kk * 32, qa[kk]);
    }

    const u32 kAddr = ksb + (u32)(((((lane >> 4) << 3) + (lane & 7)) * KVS
                                   + 8 * ((lane >> 3) & 1)) * 2);
    const u32 vAddr = vsb + (u32)(((8 * ((lane >> 3) & 1) + (lane & 7)) * KVS
                                   + 8 * (lane >> 4)) * 2);

    float oacc[8][4];
#pragma unroll
    for (int i = 0; i < 8; i++)
#pragma unroll
        for (int j = 0; j < 4; j++) oacc[i][j] = 0.f;
    float m0r = -1e30f, m1r = -1e30f, l0r = 0.f, l1r = 0.f;

    for (int it = 0; it < NIT; it++) {
        CP_WAIT0();
        __syncthreads();
        if (it + 1 < NIT) issue_tile(it + 1);

        const u32 so = (u32)((it & 1) ? KVB * 2 : 0);
        const u32 kA = kAddr + so;
        const u32 vA = vAddr + so;

        // ---- S = Q K^T : 16 x 64 in registers ----
        float sacc[8][4];
#pragma unroll
        for (int i = 0; i < 8; i++)
#pragma unroll
            for (int j = 0; j < 4; j++) sacc[i][j] = 0.f;
#pragma unroll
        for (int kk = 0; kk < 4; kk++) {
#pragma unroll
            for (int nb = 0; nb < 4; nb++) {
                u32 kb[4];
                ldm_x4(kA + (u32)((nb * 16 * KVS + kk * 16) * 2), kb);
                mma16816(sacc[nb * 2 + 0], qa[kk], kb[0], kb[1]);
                mma16816(sacc[nb * 2 + 1], qa[kk], kb[2], kb[3]);
            }
        }

        // ---- online softmax in registers ----
        float mx0 = m0r, mx1 = m1r;
#pragma unroll
        for (int nb = 0; nb < 8; nb++) {
            mx0 = fmaxf(mx0, fmaxf(sacc[nb][0], sacc[nb][1]));
            mx1 = fmaxf(mx1, fmaxf(sacc[nb][2], sacc[nb][3]));
        }
        mx0 = fmaxf(mx0, __shfl_xor_sync(0xFFFFFFFFu, mx0, 1));
        mx0 = fmaxf(mx0, __shfl_xor_sync(0xFFFFFFFFu, mx0, 2));
        mx1 = fmaxf(mx1, __shfl_xor_sync(0xFFFFFFFFu, mx1, 1));
        mx1 = fmaxf(mx1, __shfl_xor_sync(0xFFFFFFFFu, mx1, 2));

        const float sc0 = __expf(m0r - mx0);
        const float sc1 = __expf(m1r - mx1);
        m0r = mx0; m1r = mx1;

        float sum0 = 0.f, sum1 = 0.f;
#pragma unroll
        for (int nb = 0; nb < 8; nb++) {
            sacc[nb][0] = __expf(sacc[nb][0] - mx0); sum0 += sacc[nb][0];
            sacc[nb][1] = __expf(sacc[nb][1] - mx0); sum0 += sacc[nb][1];
            sacc[nb][2] = __expf(sacc[nb][2] - mx1); sum1 += sacc[nb][2];
            sacc[nb][3] = __expf(sacc[nb][3] - mx1); sum1 += sacc[nb][3];
        }
        sum0 += __shfl_xor_sync(0xFFFFFFFFu, sum0, 1);
        sum0 += __shfl_xor_sync(0xFFFFFFFFu, sum0, 2);
        sum1 += __shfl_xor_sync(0xFFFFFFFFu, sum1, 1);
        sum1 += __shfl_xor_sync(0xFFFFFFFFu, sum1, 2);
        l0r = l0r * sc0 + sum0;
        l1r = l1r * sc1 + sum1;

#pragma unroll
        for (int nb = 0; nb < 8; nb++) {
            oacc[nb][0] *= sc0; oacc[nb][1] *= sc0;
            oacc[nb][2] *= sc1; oacc[nb][3] *= sc1;
        }

        // ---- O += P V ----
#pragma unroll
        for (int kc = 0; kc < 4; kc++) {
            u32 pa[4];
            pa[0] = pkh2(sacc[kc * 2 + 0][0], sacc[kc * 2 + 0][1]);
            pa[1] = pkh2(sacc[kc * 2 + 0][2], sacc[kc * 2 + 0][3]);
            pa[2] = pkh2(sacc[kc * 2 + 1][0], sacc[kc * 2 + 1][1]);
            pa[3] = pkh2(sacc[kc * 2 + 1][2], sacc[kc * 2 + 1][3]);
#pragma unroll
            for (int dc = 0; dc < 4; dc++) {
                u32 vb[4];
                ldm_x4_t(vA + (u32)((kc * 16 * KVS + dc * 16) * 2), vb);
                mma16816(oacc[dc * 2 + 0], pa, vb[0], vb[1]);
                mma16816(oacc[dc * 2 + 1], pa, vb[2], vb[3]);
            }
        }
    }

    // ---- normalize + store fp16 ----
    {
        const float li0 = 1.0f / l0r;
        const float li1 = 1.0f / l1r;
        __half* base = g_ah + (size_t)(b * SEQ + q0 + m0 + g) * D_MODEL + h * DHEAD;
#pragma unroll
        for (int nb = 0; nb < 8; nb++) {
            const int col = nb * 8 + 2 * t4;
            *(u32*)(base + col) = pkh2(oacc[nb][0] * li0, oacc[nb][1] * li0);
            *(u32*)(base + 8 * D_MODEL + col) = pkh2(oacc[nb][2] * li1, oacc[nb][3] * li1);
        }
    }
}

// ---------------------------------------------------------------------------
extern "C" void kernel_launch(void* const* d_in, const int* in_sizes, int n_in,
                              void* d_out, int out_size)
{
    const float* hs  = (const float*)d_in[0];
    const float* Wq  = (const float*)d_in[1];
    const float* Wk  = (const float*)d_in[2];
    const float* Wv  = (const float*)d_in[3];
    const float* Wo  = (const float*)d_in[4];
    const float* bo  = (const float*)d_in[5];
    const float* Kbg = (const float*)d_in[6];
    const float* Vbg = (const float*)d_in[7];
    float* out = (float*)d_out;

    // 0) prep: weight transpose, activation + background fp16 conversion
    dim3 gw(D_MODEL / 32, D_MODEL / 32, 4);
    prep_w_kernel<<<gw, 256>>>(Wq, Wk, Wv, Wo);
    conv_kernel<<<(M_TOTAL * D_MODEL) / (256 * 8), 256>>>(hs);
    conv_bg_kernel<<<(BHEADS * SEQ * DHEAD) / (256 * 8), 256>>>(Kbg, Vbg);

    // 1) Q/K/V projections (128x64 tiles, 3 CTA/SM)
    dim3 gqkv(D_MODEL / 64, M_TOTAL / 128, 3);
    qkv_mm_kernel<<<gqkv, 256>>>();

    // 2) attention (register-resident FA2, cp.async pipelined — proven R15)
    dim3 gattn(SEQ / 128, BHEADS);
    attn_kernel<<<gattn, 256>>>();

    // 3) output projection + bias (fp32 out)
    dim3 gout(D_MODEL / 64, M_TOTAL / 128, 1);
    out_mm_kernel<<<gout, 256>>>(bo, out);
}